// round 17
// baseline (speedup 1.0000x reference)
#include <cuda_runtime.h>
#include <cuda_bf16.h>
#include <stdint.h>

// Axial attention over T: 4096 independent [128 x 128] attentions, C=128.
// HMMA bf16 split-precision (hi+lo, 3 MMAs), warp-specialized:
//   16 compute warps (512 thr): GEMM1 -> softmax -> GEMM2 -> O store
//    4 producer warps (128 thr): k-blocked Q/K load+convert, V load, attn write

#define L 128
#define CD 128
#define STRIDE_T 32768
#define NPROB 4096
#define OUT_ELEMS 67108864LL

#define NT 640                   // 512 compute + 128 producer
#define ROWB 272                 // padded row: 136 bf16 = 272 B
#define TILEB (128 * ROWB)       // 34816 B per tile
#define SM_RED 0                 // pmax[2][128], psum[2][128]
#define SM_TILE0 2048
#define QH_OFF (SM_TILE0 + 0 * TILEB)
#define QL_OFF (SM_TILE0 + 1 * TILEB)
#define KH_OFF (SM_TILE0 + 2 * TILEB)
#define KL_OFF (SM_TILE0 + 3 * TILEB)
#define VH_OFF (SM_TILE0 + 4 * TILEB)
#define VL_OFF (SM_TILE0 + 5 * TILEB)
#define SMEM_TOTAL (SM_TILE0 + 6 * TILEB)   // 210944 B

// named barriers: 1..4 = QK block kb ready (640), 5 = V ready (640),
// 6 = pmax exchange (512, compute only), 7 = P + psum ready (640)
__device__ __forceinline__ void bar_sync(int id, int cnt) {
    asm volatile("bar.sync %0, %1;" :: "r"(id), "r"(cnt) : "memory");
}
__device__ __forceinline__ void bar_arrive(int id, int cnt) {
    asm volatile("bar.arrive %0, %1;" :: "r"(id), "r"(cnt) : "memory");
}
__device__ __forceinline__ void fence_cta() {
    asm volatile("fence.acq_rel.cta;" ::: "memory");
}
__device__ __forceinline__ uint32_t smem_u32(const void* p) {
    uint32_t a;
    asm("{ .reg .u64 t; cvta.to.shared.u64 t, %1; cvt.u32.u64 %0, t; }"
        : "=r"(a) : "l"(p));
    return a;
}
// split fp32 pair (x -> lower bf16, y -> upper bf16) into hi + residual-lo words
__device__ __forceinline__ void split2(float x, float y, uint32_t& hi, uint32_t& lo) {
    uint32_t h;
    asm("cvt.rn.bf16x2.f32 %0, %1, %2;" : "=r"(h) : "f"(y), "f"(x));
    float hx = __uint_as_float(h << 16);
    float hy = __uint_as_float(h & 0xffff0000u);
    float rx = x - hx, ry = y - hy;
    asm("cvt.rn.bf16x2.f32 %0, %1, %2;" : "=r"(lo) : "f"(ry), "f"(rx));
    hi = h;
}
__device__ __forceinline__ float blo(uint32_t u) { return __uint_as_float(u << 16); }
__device__ __forceinline__ float bhi(uint32_t u) { return __uint_as_float(u & 0xffff0000u); }

__device__ __forceinline__ void ldsm4(uint32_t* r, uint32_t addr) {
    asm volatile("ldmatrix.sync.aligned.m8n8.x4.shared.b16 {%0,%1,%2,%3}, [%4];"
                 : "=r"(r[0]), "=r"(r[1]), "=r"(r[2]), "=r"(r[3]) : "r"(addr));
}
__device__ __forceinline__ void mma16816(float* d, const uint32_t* a,
                                         uint32_t b0, uint32_t b1) {
    asm volatile("mma.sync.aligned.m16n8k16.row.col.f32.bf16.bf16.f32 "
                 "{%0,%1,%2,%3}, {%4,%5,%6,%7}, {%8,%9}, {%0,%1,%2,%3};"
                 : "+f"(d[0]), "+f"(d[1]), "+f"(d[2]), "+f"(d[3])
                 : "r"(a[0]), "r"(a[1]), "r"(a[2]), "r"(a[3]), "r"(b0), "r"(b1));
}

extern __shared__ char smem[];

__global__ void __launch_bounds__(NT, 1)
axial_attn_ws(const float* __restrict__ Q, const float* __restrict__ K,
              const float* __restrict__ V, float* __restrict__ Out,
              float* __restrict__ Attn, int writeAttn)
{
    char* sm = smem;
    const uint32_t sb = smem_u32(smem);
    const int tid = threadIdx.x, wid = tid >> 5, lane = tid & 31;
    const int n = blockIdx.x;
    const size_t base = (size_t)(n >> 8) * (size_t)L * STRIDE_T
                      + (size_t)(n & 255) * CD;

    float* pmax = (float*)(sm + SM_RED);         // [2][128]
    float* psum = pmax + 256;                    // [2][128]

    if (wid >= 16) {
        // ================= PRODUCER warps (4 warps, 128 threads) =================
        const int pt = tid - 512;        // 0..127
        const int pw = wid - 16;         // 0..3
        const int f  = pt & 7;           // float4 col index within 32-col block
        const int rb = pt >> 3;          // 0..15

        // ---- Q,K in 4 k-blocks of 32 cols ----
        for (int kb = 0; kb < 4; ++kb) {
            const int c4 = 32 * kb + 4 * f;
            #pragma unroll
            for (int i = 0; i < 8; ++i) {
                const int row = rb + 16 * i;
                const size_t g = base + (size_t)row * STRIDE_T + c4;
                const float4 qv = *(const float4*)(Q + g);
                const float4 kv = *(const float4*)(K + g);
                const uint32_t off = (uint32_t)row * ROWB + (uint32_t)c4 * 2;
                uint32_t h0, l0, h1, l1;
                split2(qv.x, qv.y, h0, l0); split2(qv.z, qv.w, h1, l1);
                *(uint64_t*)(sm + QH_OFF + off) = ((uint64_t)h1 << 32) | h0;
                *(uint64_t*)(sm + QL_OFF + off) = ((uint64_t)l1 << 32) | l0;
                split2(kv.x, kv.y, h0, l0); split2(kv.z, kv.w, h1, l1);
                *(uint64_t*)(sm + KH_OFF + off) = ((uint64_t)h1 << 32) | h0;
                *(uint64_t*)(sm + KL_OFF + off) = ((uint64_t)l1 << 32) | l0;
            }
            fence_cta();
            bar_arrive(1 + kb, NT);
        }

        // ---- V^T[c][k] (coalesced gmem; transpose into smem rows c) ----
        {
            const int c = 32 * pw + lane;
            #pragma unroll 8
            for (int kk = 0; kk < 128; kk += 2) {
                const float v0 = V[base + (size_t)kk * STRIDE_T + c];
                const float v1 = V[base + (size_t)(kk + 1) * STRIDE_T + c];
                uint32_t h, l; split2(v0, v1, h, l);
                const uint32_t off = (uint32_t)c * ROWB + (uint32_t)kk * 2;
                *(uint32_t*)(sm + VH_OFF + off) = h;
                *(uint32_t*)(sm + VL_OFF + off) = l;
            }
        }
        fence_cta();
        bar_arrive(5, NT);

        // ---- wait for P tiles + psum, then write normalized attn ----
        bar_sync(7, NT);
        if (writeAttn) {
            const int rl = lane >> 3;      // 0..3
            const int cf = lane & 7;       // 0..7 float4 col
            #pragma unroll
            for (int i = 0; i < 8; ++i) {
                const int row = 32 * pw + 4 * i + rl;
                const float rv = 1.0f / (psum[row] + psum[128 + row]);
                float* arow = Attn + (size_t)n * (L * L) + (size_t)row * L;
                #pragma unroll
                for (int j = 0; j < 4; ++j) {
                    const int c4 = 4 * (cf + 8 * j);
                    const uint32_t off = (uint32_t)row * ROWB + (uint32_t)c4 * 2;
                    const uint64_t h8 = *(const uint64_t*)(sm + QH_OFF + off);
                    const uint64_t l8 = *(const uint64_t*)(sm + QL_OFF + off);
                    const uint32_t h0 = (uint32_t)h8, h1 = (uint32_t)(h8 >> 32);
                    const uint32_t l0 = (uint32_t)l8, l1 = (uint32_t)(l8 >> 32);
                    float4 w;
                    w.x = (blo(h0) + blo(l0)) * rv;
                    w.y = (bhi(h0) + bhi(l0)) * rv;
                    w.z = (blo(h1) + blo(l1)) * rv;
                    w.w = (bhi(h1) + bhi(l1)) * rv;
                    *(float4*)(arow + c4) = w;
                }
            }
        }
        return;
    }

    // ================= COMPUTE warps (16 warps, 512 threads) =================
    const int g_ = wid >> 1, nhalf = wid & 1;
    const int rsel = lane & 15, csel = lane >> 4;
    const uint32_t aAddrBase = sb + QH_OFF + (uint32_t)(16 * g_ + rsel) * ROWB + csel * 16;
    const uint32_t bAddrQK = sb + KH_OFF + (uint32_t)(64 * nhalf + rsel) * ROWB + csel * 16;
    const uint32_t bAddrPV = sb + VH_OFF + (uint32_t)(64 * nhalf + rsel) * ROWB + csel * 16;

    float acc[8][4];
    #pragma unroll
    for (int j = 0; j < 8; j++) { acc[j][0] = acc[j][1] = acc[j][2] = acc[j][3] = 0.f; }

    // ======== GEMM1: S = Q K^T, k-blocked behind producer barriers ========
    #pragma unroll
    for (int kb = 0; kb < 4; ++kb) {
        bar_sync(1 + kb, NT);
        #pragma unroll
        for (int ksl = 0; ksl < 2; ++ksl) {
            const int ks = 2 * kb + ksl;
            uint32_t aH[4], aL[4];
            const uint32_t aAddr = aAddrBase + ks * 32;
            ldsm4(aH, aAddr);
            ldsm4(aL, aAddr + TILEB);
            #pragma unroll
            for (int ng = 0; ng < 4; ++ng) {
                uint32_t bH[4], bL[4];
                const uint32_t bAddr = bAddrQK + (uint32_t)ng * (16 * ROWB) + ks * 32;
                ldsm4(bH, bAddr);
                ldsm4(bL, bAddr + TILEB);
                mma16816(acc[2*ng],     aH, bH[0], bH[2]);
                mma16816(acc[2*ng],     aH, bL[0], bL[2]);
                mma16816(acc[2*ng],     aL, bH[0], bH[2]);
                mma16816(acc[2*ng + 1], aH, bH[1], bH[3]);
                mma16816(acc[2*ng + 1], aH, bL[1], bL[3]);
                mma16816(acc[2*ng + 1], aL, bH[1], bH[3]);
            }
        }
    }

    // ======== softmax: intra-warp over 64 cols, cross-half via smem ========
    const int r = lane >> 2, cq = lane & 3;
    const int q0 = 16 * g_ + r, q1 = q0 + 8;
    float m0 = -1e30f, m1 = -1e30f;
    #pragma unroll
    for (int j = 0; j < 8; j++) {
        m0 = fmaxf(m0, fmaxf(acc[j][0], acc[j][1]));
        m1 = fmaxf(m1, fmaxf(acc[j][2], acc[j][3]));
    }
    m0 = fmaxf(m0, __shfl_xor_sync(0xffffffffu, m0, 1));
    m0 = fmaxf(m0, __shfl_xor_sync(0xffffffffu, m0, 2));
    m1 = fmaxf(m1, __shfl_xor_sync(0xffffffffu, m1, 1));
    m1 = fmaxf(m1, __shfl_xor_sync(0xffffffffu, m1, 2));
    if (cq == 0) {
        pmax[nhalf * 128 + q0] = m0;
        pmax[nhalf * 128 + q1] = m1;
    }
    bar_sync(6, 512);
    m0 = fmaxf(pmax[q0], pmax[128 + q0]);
    m1 = fmaxf(pmax[q1], pmax[128 + q1]);

    const float is = 0.08838834764831845f;   // 1/sqrt(128)
    float s0 = 0.f, s1 = 0.f;
    #pragma unroll
    for (int j = 0; j < 8; j++) {
        acc[j][0] = __expf((acc[j][0] - m0) * is);
        acc[j][1] = __expf((acc[j][1] - m0) * is);
        acc[j][2] = __expf((acc[j][2] - m1) * is);
        acc[j][3] = __expf((acc[j][3] - m1) * is);
        s0 += acc[j][0] + acc[j][1];
        s1 += acc[j][2] + acc[j][3];
    }
    // unnormalized P -> split-bf16 into the (dead) Q tiles (own rows/cols only)
    #pragma unroll
    for (int j = 0; j < 8; j++) {
        const uint32_t off = (uint32_t)(64 * nhalf + 8 * j + 2 * cq) * 2;
        uint32_t h, l;
        split2(acc[j][0], acc[j][1], h, l);
        *(uint32_t*)(sm + QH_OFF + (uint32_t)q0 * ROWB + off) = h;
        *(uint32_t*)(sm + QL_OFF + (uint32_t)q0 * ROWB + off) = l;
        split2(acc[j][2], acc[j][3], h, l);
        *(uint32_t*)(sm + QH_OFF + (uint32_t)q1 * ROWB + off) = h;
        *(uint32_t*)(sm + QL_OFF + (uint32_t)q1 * ROWB + off) = l;
    }
    s0 += __shfl_xor_sync(0xffffffffu, s0, 1);
    s0 += __shfl_xor_sync(0xffffffffu, s0, 2);
    s1 += __shfl_xor_sync(0xffffffffu, s1, 1);
    s1 += __shfl_xor_sync(0xffffffffu, s1, 2);
    if (cq == 0) {
        psum[nhalf * 128 + q0] = s0;
        psum[nhalf * 128 + q1] = s1;
    }
    fence_cta();
    bar_sync(7, NT);            // P tiles + psum ready -> releases producers for attn
    const float rv0 = 1.0f / (psum[q0] + psum[128 + q0]);
    const float rv1 = 1.0f / (psum[q1] + psum[128 + q1]);

    bar_sync(5, NT);            // V tiles ready (producer arrived long ago)

    // ======== GEMM2: O = P V (normalize in epilogue) ========
    #pragma unroll
    for (int j = 0; j < 8; j++) { acc[j][0] = acc[j][1] = acc[j][2] = acc[j][3] = 0.f; }
    #pragma unroll
    for (int ks = 0; ks < 8; ++ks) {
        uint32_t aH[4], aL[4];
        const uint32_t aAddr = aAddrBase + ks * 32;
        ldsm4(aH, aAddr);
        ldsm4(aL, aAddr + TILEB);
        #pragma unroll
        for (int ng = 0; ng < 4; ++ng) {
            uint32_t bH[4], bL[4];
            const uint32_t bAddr = bAddrPV + (uint32_t)ng * (16 * ROWB) + ks * 32;
            ldsm4(bH, bAddr);
            ldsm4(bL, bAddr + TILEB);
            mma16816(acc[2*ng],     aH, bH[0], bH[2]);
            mma16816(acc[2*ng],     aH, bL[0], bL[2]);
            mma16816(acc[2*ng],     aL, bH[0], bH[2]);
            mma16816(acc[2*ng + 1], aH, bH[1], bH[3]);
            mma16816(acc[2*ng + 1], aH, bL[1], bL[3]);
            mma16816(acc[2*ng + 1], aL, bH[1], bH[3]);
        }
    }

    // ======== epilogue: normalize rows, store O ========
    {
        float* o0 = Out + base + (size_t)q0 * STRIDE_T + 64 * nhalf;
        float* o1 = Out + base + (size_t)q1 * STRIDE_T + 64 * nhalf;
        #pragma unroll
        for (int j = 0; j < 8; j++) {
            const int col = 8 * j + 2 * cq;
            *(float2*)(o0 + col) = make_float2(acc[j][0] * rv0, acc[j][1] * rv0);
            *(float2*)(o1 + col) = make_float2(acc[j][2] * rv1, acc[j][3] * rv1);
        }
    }
}

extern "C" void kernel_launch(void* const* d_in, const int* in_sizes, int n_in,
                              void* d_out, int out_size) {
    const float* q = (const float*)d_in[0];
    const float* k = (const float*)d_in[1];
    const float* v = (const float*)d_in[2];
    float* out = (float*)d_out;

    const int writeAttn = ((long long)out_size >= 2LL * OUT_ELEMS) ? 1 : 0;
    float* attn = out + OUT_ELEMS;

    cudaFuncSetAttribute(axial_attn_ws,
                         cudaFuncAttributeMaxDynamicSharedMemorySize, SMEM_TOTAL);
    axial_attn_ws<<<NPROB, NT, SMEM_TOTAL>>>(q, k, v, out, attn, writeAttn);
}